// round 2
// baseline (speedup 1.0000x reference)
#include <cuda_runtime.h>

#define Nn 10000
#define Cc 128
#define Hh 256
#define Ee 320000

constexpr float kCutoff = 5.0f;
constexpr float kEps    = 1e-5f;
constexpr float kPi     = 3.14159265358979323846f;

// ---------------- scratch (device globals; no runtime allocation) ----------------
__device__ float g_hn  [Nn * Cc];   // LN1(h)
__device__ float g_P1  [Nn * Hh];   // hn @ We1[0:128]
__device__ float g_P2  [Nn * Hh];   // hn @ We1[128:256]
__device__ float g_sums[Nn * Hh];   // segment sums
__device__ float g_cnt [Nn];        // segment counts
__device__ float g_t   [Nn * Hh];   // node MLP hidden
__device__ float g_h1  [Nn * Cc];
__device__ float g_h2  [Nn * Cc];   // LN2(h1)
__device__ float g_u   [Nn * Hh];   // out MLP hidden

__device__ __forceinline__ float silu_f(float v) {
    return v * (1.0f / (1.0f + __expf(-v)));
}

// ---------------- zero the accumulators (graph replays must reset) ----------------
__global__ void zero_kernel() {
    int i = blockIdx.x * blockDim.x + threadIdx.x;
    if (i < Nn * Hh) g_sums[i] = 0.0f;
    if (i < Nn)      g_cnt[i]  = 0.0f;
}

// ---------------- LayerNorm over C=128, one block per row ----------------
__device__ __forceinline__ void ln_row(const float* __restrict__ in,
                                       const float* __restrict__ gg,
                                       const float* __restrict__ bb,
                                       float* __restrict__ out) {
    int n = blockIdx.x, c = threadIdx.x;
    float v = in[n * Cc + c];
    float s = v, s2 = v * v;
    #pragma unroll
    for (int o = 16; o; o >>= 1) {
        s  += __shfl_xor_sync(0xffffffffu, s,  o);
        s2 += __shfl_xor_sync(0xffffffffu, s2, o);
    }
    __shared__ float ws[4], ws2[4];
    if ((c & 31) == 0) { ws[c >> 5] = s; ws2[c >> 5] = s2; }
    __syncthreads();
    s  = ws[0]  + ws[1]  + ws[2]  + ws[3];
    s2 = ws2[0] + ws2[1] + ws2[2] + ws2[3];
    float mu  = s * (1.0f / Cc);
    float var = s2 * (1.0f / Cc) - mu * mu;
    out[n * Cc + c] = (v - mu) * rsqrtf(var + kEps) * gg[c] + bb[c];
}

__global__ void ln1_kernel(const float* __restrict__ h,
                           const float* __restrict__ g1,
                           const float* __restrict__ b1) {
    ln_row(h, g1, b1, g_hn);
}
__global__ void ln2_kernel(const float* __restrict__ g2,
                           const float* __restrict__ b2) {
    ln_row(g_h1, g2, b2, g_h2);
}

// ---------------- node projections P1/P2 = hn @ We1 halves ----------------
#define NB 8
__global__ void __launch_bounds__(256) p1p2_kernel(const float* __restrict__ We1) {
    __shared__ float sIn[NB][Cc];
    int tid = threadIdx.x;
    int n0  = blockIdx.x * NB;
    for (int idx = tid; idx < NB * Cc; idx += 256)
        sIn[idx >> 7][idx & 127] = g_hn[n0 * Cc + idx];
    __syncthreads();
    float a1[NB], a2[NB];
    #pragma unroll
    for (int p = 0; p < NB; p++) { a1[p] = 0.f; a2[p] = 0.f; }
    for (int k = 0; k < Cc; k++) {
        float w1 = We1[k * Hh + tid];
        float w2 = We1[(k + Cc) * Hh + tid];
        #pragma unroll
        for (int p = 0; p < NB; p++) {
            float v = sIn[p][k];
            a1[p] += v * w1;
            a2[p] += v * w2;
        }
    }
    #pragma unroll
    for (int p = 0; p < NB; p++) {
        g_P1[(n0 + p) * Hh + tid] = a1[p];
        g_P2[(n0 + p) * Hh + tid] = a2[p];
    }
}

// ---------------- edge kernel: layer1 (gathered) + layer2 GEMM + atomic scatter ----------------
#define EPB 64
#define KB  32
// dynamic smem: sM (64x256) + sB (32x256)
constexpr int EDGE_SMEM = (EPB * Hh + KB * Hh) * (int)sizeof(float);

__global__ void __launch_bounds__(256) edge_kernel(const float* __restrict__ x,
                                                   const int*   __restrict__ eidx,
                                                   const float* __restrict__ We1,
                                                   const float* __restrict__ be1,
                                                   const float* __restrict__ We2,
                                                   const float* __restrict__ be2) {
    extern __shared__ float sm[];
    float* sM = sm;              // [EPB][Hh]   silu(layer1)
    float* sB = sm + EPB * Hh;   // [KB][Hh]    We2 K-chunk

    __shared__ float sDist[EPB], sCcut[EPB], sWl[Hh], sBe1[Hh], sBe2[Hh];
    __shared__ int   sRow[EPB], sCol[EPB];

    int tid = threadIdx.x;
    int tx = tid & 31, ty = tid >> 5;
    int e0 = blockIdx.x * EPB;

    // per-edge scalars
    if (tid < EPB) {
        int e = e0 + tid;
        int r = eidx[e];
        int c = eidx[Ee + e];
        sRow[tid] = r;
        sCol[tid] = c;
        float dx = x[r * 3 + 0] - x[c * 3 + 0];
        float dy = x[r * 3 + 1] - x[c * 3 + 1];
        float dz = x[r * 3 + 2] - x[c * 3 + 2];
        float d  = sqrtf(dx * dx + dy * dy + dz * dz);
        sDist[tid] = d;
        float cc = 0.5f * (__cosf(d * (kPi / kCutoff)) + 1.0f);
        sCcut[tid] = (d <= kCutoff) ? cc : 0.0f;
        atomicAdd(&g_cnt[c], 1.0f);
    }
    // cache last We1 row + biases
    sWl[tid]  = We1[(2 * Cc) * Hh + tid];
    sBe1[tid] = be1[tid];
    sBe2[tid] = be2[tid];
    __syncthreads();

    // ---- layer 1 via precomputed projections: sM = silu(P1[row]+P2[col]+d*wl+b1)
    #pragma unroll
    for (int j = 0; j < 8; j++) {
        int c = j * 32 + tx;
        float wl = sWl[c], bb = sBe1[c];
        #pragma unroll
        for (int i = 0; i < 8; i++) {
            int e = ty * 8 + i;
            float v = g_P1[sRow[e] * Hh + c] + g_P2[sCol[e] * Hh + c]
                    + sDist[e] * wl + bb;
            sM[e * Hh + c] = silu_f(v);
        }
    }

    // ---- layer 2: acc[64x256] = sM @ We2 + be2
    float acc[8][8];
    #pragma unroll
    for (int j = 0; j < 8; j++) {
        float bb = sBe2[j * 32 + tx];
        #pragma unroll
        for (int i = 0; i < 8; i++) acc[i][j] = bb;
    }

    for (int kc = 0; kc < Hh / KB; kc++) {
        int k0 = kc * KB;
        // stage We2 chunk [KB][Hh]
        #pragma unroll
        for (int it = 0; it < (KB * Hh) / 256; it++) {
            int idx = tid + it * 256;
            sB[idx] = We2[(k0 + (idx >> 8)) * Hh + (idx & 255)];
        }
        __syncthreads();
        #pragma unroll
        for (int kk = 0; kk < KB; kk++) {
            float a[8], b[8];
            #pragma unroll
            for (int i = 0; i < 8; i++) a[i] = sM[(ty * 8 + i) * Hh + k0 + kk];
            #pragma unroll
            for (int j = 0; j < 8; j++) b[j] = sB[kk * Hh + j * 32 + tx];
            #pragma unroll
            for (int i = 0; i < 8; i++)
                #pragma unroll
                for (int j = 0; j < 8; j++)
                    acc[i][j] += a[i] * b[j];
        }
        __syncthreads();
    }

    // ---- silu * cutoff, scatter-add into segment sums
    #pragma unroll
    for (int i = 0; i < 8; i++) {
        int e = ty * 8 + i;
        float cc = sCcut[e];
        int base = sCol[e] * Hh;
        #pragma unroll
        for (int j = 0; j < 8; j++) {
            float v = silu_f(acc[i][j]) * cc;
            atomicAdd(&g_sums[base + j * 32 + tx], v);
        }
    }
}

// ---------------- node MLP layer 1: t = silu([hn, m_aggr] @ Wn1 + bn1) ----------------
__global__ void __launch_bounds__(256) nmlp1_kernel(const float* __restrict__ Wn1,
                                                    const float* __restrict__ bn1) {
    __shared__ float sIn[NB][Cc + Hh];   // [8][384]
    __shared__ float sInv[NB];
    int tid = threadIdx.x;
    int n0  = blockIdx.x * NB;
    if (tid < NB) sInv[tid] = 1.0f / fmaxf(g_cnt[n0 + tid], 1.0f);
    __syncthreads();
    for (int idx = tid; idx < NB * (Cc + Hh); idx += 256) {
        int p = idx / (Cc + Hh);
        int k = idx - p * (Cc + Hh);
        int n = n0 + p;
        float v = (k < Cc) ? g_hn[n * Cc + k]
                           : g_sums[n * Hh + (k - Cc)] * sInv[p];
        sIn[p][k] = v;
    }
    __syncthreads();
    float acc[NB];
    #pragma unroll
    for (int p = 0; p < NB; p++) acc[p] = bn1[tid];
    for (int k = 0; k < Cc + Hh; k++) {
        float w = Wn1[k * Hh + tid];
        #pragma unroll
        for (int p = 0; p < NB; p++) acc[p] += sIn[p][k] * w;
    }
    #pragma unroll
    for (int p = 0; p < NB; p++)
        g_t[(n0 + p) * Hh + tid] = silu_f(acc[p]);
}

// ---------------- node MLP layer 2 + residuals: h1 = h + hn + (t @ Wn2 + bn2) ----------------
__global__ void __launch_bounds__(128) nmlp2_kernel(const float* __restrict__ h,
                                                    const float* __restrict__ Wn2,
                                                    const float* __restrict__ bn2) {
    __shared__ float sT[NB][Hh];
    int tid = threadIdx.x;
    int n0  = blockIdx.x * NB;
    for (int idx = tid; idx < NB * Hh; idx += 128)
        sT[idx >> 8][idx & 255] = g_t[n0 * Hh + idx];
    __syncthreads();
    float acc[NB];
    #pragma unroll
    for (int p = 0; p < NB; p++) acc[p] = bn2[tid];
    for (int k = 0; k < Hh; k++) {
        float w = Wn2[k * Cc + tid];
        #pragma unroll
        for (int p = 0; p < NB; p++) acc[p] += sT[p][k] * w;
    }
    #pragma unroll
    for (int p = 0; p < NB; p++) {
        int n = n0 + p;
        g_h1[n * Cc + tid] = h[n * Cc + tid] + g_hn[n * Cc + tid] + acc[p];
    }
}

// ---------------- out MLP layer 1: u = silu(h2 @ Wm1 + bm1) ----------------
__global__ void __launch_bounds__(256) mmlp1_kernel(const float* __restrict__ Wm1,
                                                    const float* __restrict__ bm1) {
    __shared__ float sIn[NB][Cc];
    int tid = threadIdx.x;
    int n0  = blockIdx.x * NB;
    for (int idx = tid; idx < NB * Cc; idx += 256)
        sIn[idx >> 7][idx & 127] = g_h2[n0 * Cc + idx];
    __syncthreads();
    float acc[NB];
    #pragma unroll
    for (int p = 0; p < NB; p++) acc[p] = bm1[tid];
    for (int k = 0; k < Cc; k++) {
        float w = Wm1[k * Hh + tid];
        #pragma unroll
        for (int p = 0; p < NB; p++) acc[p] += sIn[p][k] * w;
    }
    #pragma unroll
    for (int p = 0; p < NB; p++)
        g_u[(n0 + p) * Hh + tid] = silu_f(acc[p]);
}

// ---------------- out MLP layer 2 + final residual: out = h1 + (u @ Wm2 + bm2) ----------------
__global__ void __launch_bounds__(128) mmlp2_kernel(const float* __restrict__ Wm2,
                                                    const float* __restrict__ bm2,
                                                    float* __restrict__ out) {
    __shared__ float sU[NB][Hh];
    int tid = threadIdx.x;
    int n0  = blockIdx.x * NB;
    for (int idx = tid; idx < NB * Hh; idx += 128)
        sU[idx >> 8][idx & 255] = g_u[n0 * Hh + idx];
    __syncthreads();
    float acc[NB];
    #pragma unroll
    for (int p = 0; p < NB; p++) acc[p] = bm2[tid];
    for (int k = 0; k < Hh; k++) {
        float w = Wm2[k * Cc + tid];
        #pragma unroll
        for (int p = 0; p < NB; p++) acc[p] += sU[p][k] * w;
    }
    #pragma unroll
    for (int p = 0; p < NB; p++) {
        int n = n0 + p;
        out[n * Cc + tid] = g_h1[n * Cc + tid] + acc[p];
    }
}

// ---------------- launch ----------------
extern "C" void kernel_launch(void* const* d_in, const int* in_sizes, int n_in,
                              void* d_out, int out_size) {
    const float* x     = (const float*)d_in[0];
    const float* h     = (const float*)d_in[1];
    const int*   eidx  = (const int*)  d_in[2];
    const float* We1   = (const float*)d_in[3];
    const float* be1   = (const float*)d_in[4];
    const float* We2   = (const float*)d_in[5];
    const float* be2   = (const float*)d_in[6];
    const float* Wn1   = (const float*)d_in[7];
    const float* bn1   = (const float*)d_in[8];
    const float* Wn2   = (const float*)d_in[9];
    const float* bn2   = (const float*)d_in[10];
    const float* Wm1   = (const float*)d_in[11];
    const float* bm1   = (const float*)d_in[12];
    const float* Wm2   = (const float*)d_in[13];
    const float* bm2   = (const float*)d_in[14];
    const float* g1    = (const float*)d_in[15];
    const float* beta1 = (const float*)d_in[16];
    const float* g2    = (const float*)d_in[17];
    const float* beta2 = (const float*)d_in[18];

    cudaFuncSetAttribute(edge_kernel,
                         cudaFuncAttributeMaxDynamicSharedMemorySize, EDGE_SMEM);

    zero_kernel<<<(Nn * Hh + 1023) / 1024, 1024>>>();
    ln1_kernel<<<Nn, Cc>>>(h, g1, beta1);
    p1p2_kernel<<<Nn / NB, 256>>>(We1);
    edge_kernel<<<Ee / EPB, 256, EDGE_SMEM>>>(x, eidx, We1, be1, We2, be2);
    nmlp1_kernel<<<Nn / NB, 256>>>(Wn1, bn1);
    nmlp2_kernel<<<Nn / NB, 128>>>(h, Wn2, bn2);
    ln2_kernel<<<Nn, Cc>>>(g2, beta2);
    mmlp1_kernel<<<Nn / NB, 256>>>(Wm1, bm1);
    mmlp2_kernel<<<Nn / NB, 128>>>(Wm2, bm2, (float*)d_out);
}

// round 4
// speedup vs baseline: 1.6647x; 1.6647x over previous
#include <cuda_runtime.h>
#include <cstdint>

#define Nn 10000
#define Cc 128
#define Hh 256
#define Ee 320000

constexpr float kCutoff = 5.0f;
constexpr float kEps    = 1e-5f;
constexpr float kPi     = 3.14159265358979323846f;

// ---------------- scratch (device globals; no runtime allocation) ----------------
__device__ float g_hn  [Nn * Cc];   // LN1(h)
__device__ float g_P1  [Nn * Hh];   // hn @ We1[0:128]
__device__ float g_P2  [Nn * Hh];   // hn @ We1[128:256]
__device__ float g_sums[Nn * Hh];   // segment sums
__device__ float g_cnt [Nn];        // segment counts
__device__ float g_t   [Nn * Hh];   // node MLP hidden
__device__ float g_h1  [Nn * Cc];
__device__ float g_h2  [Nn * Cc];   // LN2(h1)
__device__ float g_u   [Nn * Hh];   // out MLP hidden

__device__ __forceinline__ float silu_f(float v) {
    return v * (1.0f / (1.0f + __expf(-v)));
}
__device__ __forceinline__ uint32_t f2tf32(float f) {
    uint32_t r; asm("cvt.rna.tf32.f32 %0, %1;" : "=r"(r) : "f"(f)); return r;
}
// tf32 m16n8k8 mma.sync (non-'a' feature; maps to fallback HMMA on sm_103)
__device__ __forceinline__ void mma_tf32(float& c0, float& c1, float& c2, float& c3,
                                         uint32_t a0, uint32_t a1, uint32_t a2, uint32_t a3,
                                         uint32_t b0, uint32_t b1) {
    asm volatile(
        "mma.sync.aligned.m16n8k8.row.col.f32.tf32.tf32.f32 "
        "{%0,%1,%2,%3}, {%4,%5,%6,%7}, {%8,%9}, {%0,%1,%2,%3};"
        : "+f"(c0), "+f"(c1), "+f"(c2), "+f"(c3)
        : "r"(a0), "r"(a1), "r"(a2), "r"(a3), "r"(b0), "r"(b1));
}

// ---------------- zero the accumulators (graph replays must reset) ----------------
__global__ void zero_kernel() {
    int i = blockIdx.x * blockDim.x + threadIdx.x;
    if (i < Nn * Hh) g_sums[i] = 0.0f;
    if (i < Nn)      g_cnt[i]  = 0.0f;
}

// ---------------- LayerNorm over C=128, one block per row ----------------
__device__ __forceinline__ void ln_row(const float* __restrict__ in,
                                       const float* __restrict__ gg,
                                       const float* __restrict__ bb,
                                       float* __restrict__ out) {
    int n = blockIdx.x, c = threadIdx.x;
    float v = in[n * Cc + c];
    float s = v, s2 = v * v;
    #pragma unroll
    for (int o = 16; o; o >>= 1) {
        s  += __shfl_xor_sync(0xffffffffu, s,  o);
        s2 += __shfl_xor_sync(0xffffffffu, s2, o);
    }
    __shared__ float ws[4], ws2[4];
    if ((c & 31) == 0) { ws[c >> 5] = s; ws2[c >> 5] = s2; }
    __syncthreads();
    s  = ws[0]  + ws[1]  + ws[2]  + ws[3];
    s2 = ws2[0] + ws2[1] + ws2[2] + ws2[3];
    float mu  = s * (1.0f / Cc);
    float var = s2 * (1.0f / Cc) - mu * mu;
    out[n * Cc + c] = (v - mu) * rsqrtf(var + kEps) * gg[c] + bb[c];
}

__global__ void ln1_kernel(const float* __restrict__ h,
                           const float* __restrict__ g1,
                           const float* __restrict__ b1) {
    ln_row(h, g1, b1, g_hn);
}
__global__ void ln2_kernel(const float* __restrict__ g2,
                           const float* __restrict__ b2) {
    ln_row(g_h1, g2, b2, g_h2);
}

// ---------------- node projections P1/P2 = hn @ We1 halves ----------------
#define NB 8
__global__ void __launch_bounds__(256) p1p2_kernel(const float* __restrict__ We1) {
    __shared__ float sIn[NB][Cc];
    int tid = threadIdx.x;
    int n0  = blockIdx.x * NB;
    for (int idx = tid; idx < NB * Cc; idx += 256)
        sIn[idx >> 7][idx & 127] = g_hn[n0 * Cc + idx];
    __syncthreads();
    float a1[NB], a2[NB];
    #pragma unroll
    for (int p = 0; p < NB; p++) { a1[p] = 0.f; a2[p] = 0.f; }
    for (int k = 0; k < Cc; k++) {
        float w1 = We1[k * Hh + tid];
        float w2 = We1[(k + Cc) * Hh + tid];
        #pragma unroll
        for (int p = 0; p < NB; p++) {
            float v = sIn[p][k];
            a1[p] += v * w1;
            a2[p] += v * w2;
        }
    }
    #pragma unroll
    for (int p = 0; p < NB; p++) {
        g_P1[(n0 + p) * Hh + tid] = a1[p];
        g_P2[(n0 + p) * Hh + tid] = a2[p];
    }
}

// ---------------- edge kernel: layer1 gather -> tf32 mma.sync GEMM -> silu*cutoff -> scatter ----
#define EPB 128                 // edges per CTA (GEMM M)
#define KC  32                  // K-chunk rows
#define AST 260                 // padded row stride (floats) for A and B smem
constexpr int A_SMEM_U32 = EPB * AST;        // 33280 u32 = 133120 B
constexpr int B_SMEM_U32 = KC * AST;         // 8320 u32  = 33280 B each
constexpr int EDGE_DSMEM = (A_SMEM_U32 + 2 * B_SMEM_U32) * 4 + 256;

__global__ void __launch_bounds__(512, 1) edge_kernel(const float* __restrict__ x,
                                                      const int*   __restrict__ eidx,
                                                      const float* __restrict__ We1,
                                                      const float* __restrict__ be1,
                                                      const float* __restrict__ We2,
                                                      const float* __restrict__ be2) {
    extern __shared__ uint32_t dynbuf[];
    uint32_t* As = dynbuf;                       // [128][AST] tf32
    uint32_t* Bs[2] = { dynbuf + A_SMEM_U32,
                        dynbuf + A_SMEM_U32 + B_SMEM_U32 };

    __shared__ float sDist[EPB], sCcut[EPB], sWl[Hh], sBe1[Hh], sBe2[Hh];
    __shared__ int   sRow[EPB], sCol[EPB];

    int tid  = threadIdx.x;
    int lane = tid & 31;
    int w    = tid >> 5;          // 0..15
    int wm   = w & 3;             // M strip: rows 32*wm..32*wm+31
    int wn   = w >> 2;            // N strip: cols 64*wn..64*wn+63
    int e0   = blockIdx.x * EPB;

    // per-edge scalars
    if (tid < EPB) {
        int e = e0 + tid;
        int r = eidx[e];
        int c = eidx[Ee + e];
        sRow[tid] = r;
        sCol[tid] = c;
        float dx = x[r * 3 + 0] - x[c * 3 + 0];
        float dy = x[r * 3 + 1] - x[c * 3 + 1];
        float dz = x[r * 3 + 2] - x[c * 3 + 2];
        float d  = sqrtf(dx * dx + dy * dy + dz * dz);
        sDist[tid] = d;
        float cc = 0.5f * (__cosf(d * (kPi / kCutoff)) + 1.0f);
        sCcut[tid] = (d <= kCutoff) ? cc : 0.0f;
        atomicAdd(&g_cnt[c], 1.0f);
    }
    if (tid < Hh) {
        sWl[tid]  = We1[(2 * Cc) * Hh + tid];
        sBe1[tid] = be1[tid];
        sBe2[tid] = be2[tid];
    }

    // stage B chunk 0 (tf32)  : rows 0..31 of We2[k][n]
    {
        // 32*256 floats / 512 threads = 4 float4 each
        #pragma unroll
        for (int i = 0; i < 4; i++) {
            int idx4 = tid + i * 512;            // 0..2047 float4 index
            int k = idx4 >> 6;                   // /64 (256/4 per row)
            int n4 = (idx4 & 63) << 2;
            float4 v = *(const float4*)(We2 + k * Hh + n4);
            uint32_t* dst = Bs[0] + k * AST + n4;
            dst[0] = f2tf32(v.x); dst[1] = f2tf32(v.y);
            dst[2] = f2tf32(v.z); dst[3] = f2tf32(v.w);
        }
    }
    __syncthreads();   // sRow/sCol/sDist/sWl visible

    // ---- A tile: silu(P1[row] + P2[col] + d*wl + b1) -> tf32
    #pragma unroll 1
    for (int ei = 0; ei < 8; ei++) {
        int e = w * 8 + ei;
        float d = sDist[e];
        const float4* p1 = (const float4*)(g_P1 + sRow[e] * Hh);
        const float4* p2 = (const float4*)(g_P2 + sCol[e] * Hh);
        #pragma unroll
        for (int g = 0; g < 2; g++) {
            int k4 = g * 32 + lane;
            float4 a  = p1[k4];
            float4 b2 = p2[k4];
            float4 wl = ((const float4*)sWl)[k4];
            float4 bb = ((const float4*)sBe1)[k4];
            uint32_t* dst = As + e * AST + k4 * 4;
            dst[0] = f2tf32(silu_f(a.x + b2.x + d * wl.x + bb.x));
            dst[1] = f2tf32(silu_f(a.y + b2.y + d * wl.y + bb.y));
            dst[2] = f2tf32(silu_f(a.z + b2.z + d * wl.z + bb.z));
            dst[3] = f2tf32(silu_f(a.w + b2.w + d * wl.w + bb.w));
        }
    }
    __syncthreads();

    // ---- mainloop: 8 K-chunks of 32, double-buffered B
    float acc[2][8][4];
    #pragma unroll
    for (int mt = 0; mt < 2; mt++)
        #pragma unroll
        for (int nt = 0; nt < 8; nt++)
            #pragma unroll
            for (int q = 0; q < 4; q++) acc[mt][nt][q] = 0.0f;

    int ar0 = 32 * wm + (lane >> 2);
    int bc0 = 64 * wn + (lane >> 2);

    #pragma unroll 1
    for (int kc = 0; kc < 8; kc++) {
        // prefetch next B chunk into the other buffer (loads overlap HMMA below)
        if (kc < 7) {
            uint32_t* dstB = Bs[(kc + 1) & 1];
            const float* srcB = We2 + (kc + 1) * KC * Hh;
            #pragma unroll
            for (int i = 0; i < 4; i++) {
                int idx4 = tid + i * 512;
                int k = idx4 >> 6;
                int n4 = (idx4 & 63) << 2;
                float4 v = *(const float4*)(srcB + k * Hh + n4);
                uint32_t* dst = dstB + k * AST + n4;
                dst[0] = f2tf32(v.x); dst[1] = f2tf32(v.y);
                dst[2] = f2tf32(v.z); dst[3] = f2tf32(v.w);
            }
        }
        const uint32_t* Bcur = Bs[kc & 1];
        #pragma unroll
        for (int step = 0; step < 4; step++) {
            int kk = step * 8;                       // within chunk
            int ac = kc * KC + kk + (lane & 3);      // global K col in A
            uint32_t a[2][4];
            #pragma unroll
            for (int mt = 0; mt < 2; mt++) {
                const uint32_t* Ab = As + (ar0 + 16 * mt) * AST + ac;
                a[mt][0] = Ab[0];
                a[mt][1] = Ab[8 * AST];
                a[mt][2] = Ab[4];
                a[mt][3] = Ab[8 * AST + 4];
            }
            uint32_t b[8][2];
            const uint32_t* Bb = Bcur + (kk + (lane & 3)) * AST + bc0;
            #pragma unroll
            for (int nt = 0; nt < 8; nt++) {
                b[nt][0] = Bb[8 * nt];
                b[nt][1] = Bb[4 * AST + 8 * nt];
            }
            #pragma unroll
            for (int mt = 0; mt < 2; mt++)
                #pragma unroll
                for (int nt = 0; nt < 8; nt++)
                    mma_tf32(acc[mt][nt][0], acc[mt][nt][1],
                             acc[mt][nt][2], acc[mt][nt][3],
                             a[mt][0], a[mt][1], a[mt][2], a[mt][3],
                             b[nt][0], b[nt][1]);
        }
        __syncthreads();
    }

    // ---- epilogue: +bias, silu, *cutoff, scatter-add
    #pragma unroll
    for (int mt = 0; mt < 2; mt++) {
        int r0 = 32 * wm + 16 * mt + (lane >> 2);   // edge row for c0/c1
        int r1 = r0 + 8;                            // edge row for c2/c3
        float cc0 = sCcut[r0], cc1 = sCcut[r1];
        int base0 = sCol[r0] * Hh, base1 = sCol[r1] * Hh;
        #pragma unroll
        for (int nt = 0; nt < 8; nt++) {
            int col = 64 * wn + 8 * nt + 2 * (lane & 3);
            float b0 = sBe2[col], b1 = sBe2[col + 1];
            atomicAdd(&g_sums[base0 + col],     silu_f(acc[mt][nt][0] + b0) * cc0);
            atomicAdd(&g_sums[base0 + col + 1], silu_f(acc[mt][nt][1] + b1) * cc0);
            atomicAdd(&g_sums[base1 + col],     silu_f(acc[mt][nt][2] + b0) * cc1);
            atomicAdd(&g_sums[base1 + col + 1], silu_f(acc[mt][nt][3] + b1) * cc1);
        }
    }
}

// ---------------- node MLP layer 1: t = silu([hn, m_aggr] @ Wn1 + bn1) ----------------
__global__ void __launch_bounds__(256) nmlp1_kernel(const float* __restrict__ Wn1,
                                                    const float* __restrict__ bn1) {
    __shared__ float sIn[NB][Cc + Hh];   // [8][384]
    __shared__ float sInv[NB];
    int tid = threadIdx.x;
    int n0  = blockIdx.x * NB;
    if (tid < NB) sInv[tid] = 1.0f / fmaxf(g_cnt[n0 + tid], 1.0f);
    __syncthreads();
    for (int idx = tid; idx < NB * (Cc + Hh); idx += 256) {
        int p = idx / (Cc + Hh);
        int k = idx - p * (Cc + Hh);
        int n = n0 + p;
        float v = (k < Cc) ? g_hn[n * Cc + k]
                           : g_sums[n * Hh + (k - Cc)] * sInv[p];
        sIn[p][k] = v;
    }
    __syncthreads();
    float acc[NB];
    #pragma unroll
    for (int p = 0; p < NB; p++) acc[p] = bn1[tid];
    for (int k = 0; k < Cc + Hh; k++) {
        float wv = Wn1[k * Hh + tid];
        #pragma unroll
        for (int p = 0; p < NB; p++) acc[p] += sIn[p][k] * wv;
    }
    #pragma unroll
    for (int p = 0; p < NB; p++)
        g_t[(n0 + p) * Hh + tid] = silu_f(acc[p]);
}

// ---------------- node MLP layer 2 + residuals ----------------
__global__ void __launch_bounds__(128) nmlp2_kernel(const float* __restrict__ h,
                                                    const float* __restrict__ Wn2,
                                                    const float* __restrict__ bn2) {
    __shared__ float sT[NB][Hh];
    int tid = threadIdx.x;
    int n0  = blockIdx.x * NB;
    for (int idx = tid; idx < NB * Hh; idx += 128)
        sT[idx >> 8][idx & 255] = g_t[n0 * Hh + idx];
    __syncthreads();
    float acc[NB];
    #pragma unroll
    for (int p = 0; p < NB; p++) acc[p] = bn2[tid];
    for (int k = 0; k < Hh; k++) {
        float wv = Wn2[k * Cc + tid];
        #pragma unroll
        for (int p = 0; p < NB; p++) acc[p] += sT[p][k] * wv;
    }
    #pragma unroll
    for (int p = 0; p < NB; p++) {
        int n = n0 + p;
        g_h1[n * Cc + tid] = h[n * Cc + tid] + g_hn[n * Cc + tid] + acc[p];
    }
}

// ---------------- out MLP layer 1 ----------------
__global__ void __launch_bounds__(256) mmlp1_kernel(const float* __restrict__ Wm1,
                                                    const float* __restrict__ bm1) {
    __shared__ float sIn[NB][Cc];
    int tid = threadIdx.x;
    int n0  = blockIdx.x * NB;
    for (int idx = tid; idx < NB * Cc; idx += 256)
        sIn[idx >> 7][idx & 127] = g_h2[n0 * Cc + idx];
    __syncthreads();
    float acc[NB];
    #pragma unroll
    for (int p = 0; p < NB; p++) acc[p] = bm1[tid];
    for (int k = 0; k < Cc; k++) {
        float wv = Wm1[k * Hh + tid];
        #pragma unroll
        for (int p = 0; p < NB; p++) acc[p] += sIn[p][k] * wv;
    }
    #pragma unroll
    for (int p = 0; p < NB; p++)
        g_u[(n0 + p) * Hh + tid] = silu_f(acc[p]);
}

// ---------------- out MLP layer 2 + final residual ----------------
__global__ void __launch_bounds__(128) mmlp2_kernel(const float* __restrict__ Wm2,
                                                    const float* __restrict__ bm2,
                                                    float* __restrict__ out) {
    __shared__ float sU[NB][Hh];
    int tid = threadIdx.x;
    int n0  = blockIdx.x * NB;
    for (int idx = tid; idx < NB * Hh; idx += 128)
        sU[idx >> 8][idx & 255] = g_u[n0 * Hh + idx];
    __syncthreads();
    float acc[NB];
    #pragma unroll
    for (int p = 0; p < NB; p++) acc[p] = bm2[tid];
    for (int k = 0; k < Hh; k++) {
        float wv = Wm2[k * Cc + tid];
        #pragma unroll
        for (int p = 0; p < NB; p++) acc[p] += sU[p][k] * wv;
    }
    #pragma unroll
    for (int p = 0; p < NB; p++) {
        int n = n0 + p;
        out[n * Cc + tid] = g_h1[n * Cc + tid] + acc[p];
    }
}

// ---------------- launch ----------------
extern "C" void kernel_launch(void* const* d_in, const int* in_sizes, int n_in,
                              void* d_out, int out_size) {
    const float* x     = (const float*)d_in[0];
    const float* h     = (const float*)d_in[1];
    const int*   eidx  = (const int*)  d_in[2];
    const float* We1   = (const float*)d_in[3];
    const float* be1   = (const float*)d_in[4];
    const float* We2   = (const float*)d_in[5];
    const float* be2   = (const float*)d_in[6];
    const float* Wn1   = (const float*)d_in[7];
    const float* bn1   = (const float*)d_in[8];
    const float* Wn2   = (const float*)d_in[9];
    const float* bn2   = (const float*)d_in[10];
    const float* Wm1   = (const float*)d_in[11];
    const float* bm1   = (const float*)d_in[12];
    const float* Wm2   = (const float*)d_in[13];
    const float* bm2   = (const float*)d_in[14];
    const float* g1    = (const float*)d_in[15];
    const float* beta1 = (const float*)d_in[16];
    const float* g2    = (const float*)d_in[17];
    const float* beta2 = (const float*)d_in[18];

    static int attr_done = 0;
    if (!attr_done) {
        cudaFuncSetAttribute(edge_kernel,
                             cudaFuncAttributeMaxDynamicSharedMemorySize, EDGE_DSMEM);
        attr_done = 1;
    }

    zero_kernel<<<(Nn * Hh + 1023) / 1024, 1024>>>();
    ln1_kernel<<<Nn, Cc>>>(h, g1, beta1);
    p1p2_kernel<<<Nn / NB, 256>>>(We1);
    edge_kernel<<<Ee / EPB, 512, EDGE_DSMEM>>>(x, eidx, We1, be1, We2, be2);
    nmlp1_kernel<<<Nn / NB, 256>>>(Wn1, bn1);
    nmlp2_kernel<<<Nn / NB, 128>>>(h, Wn2, bn2);
    ln2_kernel<<<Nn, Cc>>>(g2, beta2);
    mmlp1_kernel<<<Nn / NB, 256>>>(Wm1, bm1);
    mmlp2_kernel<<<Nn / NB, 128>>>(Wm2, bm2, (float*)d_out);
}

// round 8
// speedup vs baseline: 1.7941x; 1.0777x over previous
#include <cuda_runtime.h>
#include <cstdint>

#define Nn 10000
#define Cc 128
#define Hh 256
#define Ee 320000

constexpr float kCutoff = 5.0f;
constexpr float kEps    = 1e-5f;
constexpr float kPi     = 3.14159265358979323846f;

// ---------------- scratch (device globals; no runtime allocation) ----------------
__device__ float g_hn  [Nn * Cc];   // LN1(h)
__device__ float g_P1  [Nn * Hh];   // hn @ We1[0:128]
__device__ float g_P2  [Nn * Hh];   // hn @ We1[128:256]
__device__ float g_sums[Nn * Hh];   // segment sums
__device__ float g_cnt [Nn];        // segment counts
__device__ float g_t   [Nn * Hh];   // node MLP hidden
__device__ float g_h1  [Nn * Cc];
__device__ float g_h2  [Nn * Cc];   // LN2(h1)
__device__ float g_u   [Nn * Hh];   // out MLP hidden
__device__ uint32_t g_We2tf[Hh * Hh];  // We2 pre-converted to tf32 (rna), row-major [k][n]

__device__ __forceinline__ float silu_f(float v) {
    return v * (1.0f / (1.0f + __expf(-v)));
}
__device__ __forceinline__ uint32_t f2tf32(float f) {
    uint32_t r; asm("cvt.rna.tf32.f32 %0, %1;" : "=r"(r) : "f"(f)); return r;
}
__device__ __forceinline__ void cp_async16(uint32_t dst, const void* src) {
    asm volatile("cp.async.ca.shared.global [%0], [%1], 16;"
                 :: "r"(dst), "l"(src) : "memory");
}
// tf32 m16n8k8 mma.sync
__device__ __forceinline__ void mma_tf32(float& c0, float& c1, float& c2, float& c3,
                                         uint32_t a0, uint32_t a1, uint32_t a2, uint32_t a3,
                                         uint32_t b0, uint32_t b1) {
    asm volatile(
        "mma.sync.aligned.m16n8k8.row.col.f32.tf32.tf32.f32 "
        "{%0,%1,%2,%3}, {%4,%5,%6,%7}, {%8,%9}, {%0,%1,%2,%3};"
        : "+f"(c0), "+f"(c1), "+f"(c2), "+f"(c3)
        : "r"(a0), "r"(a1), "r"(a2), "r"(a3), "r"(b0), "r"(b1));
}

// ---------------- zero the accumulators (graph replays must reset) ----------------
__global__ void zero_kernel() {
    int i = blockIdx.x * blockDim.x + threadIdx.x;
    if (i < Nn * Hh) g_sums[i] = 0.0f;
    if (i < Nn)      g_cnt[i]  = 0.0f;
}

// ---------------- We2 -> tf32 (rna) once ----------------
__global__ void prepWe2_kernel(const float* __restrict__ We2) {
    int i = blockIdx.x * 1024 + threadIdx.x;
    if (i < Hh * Hh) g_We2tf[i] = f2tf32(We2[i]);
}

// ---------------- LayerNorm over C=128, one block per row ----------------
__device__ __forceinline__ void ln_row(const float* __restrict__ in,
                                       const float* __restrict__ gg,
                                       const float* __restrict__ bb,
                                       float* __restrict__ out) {
    int n = blockIdx.x, c = threadIdx.x;
    float v = in[n * Cc + c];
    float s = v, s2 = v * v;
    #pragma unroll
    for (int o = 16; o; o >>= 1) {
        s  += __shfl_xor_sync(0xffffffffu, s,  o);
        s2 += __shfl_xor_sync(0xffffffffu, s2, o);
    }
    __shared__ float ws[4], ws2[4];
    if ((c & 31) == 0) { ws[c >> 5] = s; ws2[c >> 5] = s2; }
    __syncthreads();
    s  = ws[0]  + ws[1]  + ws[2]  + ws[3];
    s2 = ws2[0] + ws2[1] + ws2[2] + ws2[3];
    float mu  = s * (1.0f / Cc);
    float var = s2 * (1.0f / Cc) - mu * mu;
    out[n * Cc + c] = (v - mu) * rsqrtf(var + kEps) * gg[c] + bb[c];
}

__global__ void ln1_kernel(const float* __restrict__ h,
                           const float* __restrict__ g1,
                           const float* __restrict__ b1) {
    ln_row(h, g1, b1, g_hn);
}
__global__ void ln2_kernel(const float* __restrict__ g2,
                           const float* __restrict__ b2) {
    ln_row(g_h1, g2, b2, g_h2);
}

// ---------------- node projections P1/P2 = hn @ We1 halves ----------------
#define NB 8
__global__ void __launch_bounds__(256) p1p2_kernel(const float* __restrict__ We1) {
    __shared__ float sIn[NB][Cc];
    int tid = threadIdx.x;
    int n0  = blockIdx.x * NB;
    for (int idx = tid; idx < NB * Cc; idx += 256)
        sIn[idx >> 7][idx & 127] = g_hn[n0 * Cc + idx];
    __syncthreads();
    float a1[NB], a2[NB];
    #pragma unroll
    for (int p = 0; p < NB; p++) { a1[p] = 0.f; a2[p] = 0.f; }
    for (int k = 0; k < Cc; k++) {
        float w1 = We1[k * Hh + tid];
        float w2 = We1[(k + Cc) * Hh + tid];
        #pragma unroll
        for (int p = 0; p < NB; p++) {
            float v = sIn[p][k];
            a1[p] += v * w1;
            a2[p] += v * w2;
        }
    }
    #pragma unroll
    for (int p = 0; p < NB; p++) {
        g_P1[(n0 + p) * Hh + tid] = a1[p];
        g_P2[(n0 + p) * Hh + tid] = a2[p];
    }
}

// ---------------- edge kernel: layer1 gather -> tf32 mma.sync GEMM -> silu*cutoff -> scatter ----
#define EPB  64                 // edges per CTA (GEMM M)
#define KC   16                 // K-chunk rows
#define ASTA 260                // A smem row stride (floats): banks 4r+c conflict-free
#define ASTB 264                // B smem row stride (floats): banks 8r+c conflict-free
constexpr int A_SMEM_U32 = EPB * ASTA;       // 16640 u32
constexpr int B_SMEM_U32 = KC * ASTB;        // 4224 u32 each
constexpr int EDGE_DSMEM = (A_SMEM_U32 + 2 * B_SMEM_U32) * 4;   // 100352 B

__global__ void __launch_bounds__(256, 2) edge_kernel(const float* __restrict__ x,
                                                      const int*   __restrict__ eidx,
                                                      const float* __restrict__ We1,
                                                      const float* __restrict__ be1,
                                                      const float* __restrict__ be2) {
    extern __shared__ __align__(16) uint32_t dynbuf[];
    uint32_t* As = dynbuf;                       // [64][ASTA] tf32
    uint32_t* Bs[2] = { dynbuf + A_SMEM_U32,
                        dynbuf + A_SMEM_U32 + B_SMEM_U32 };

    __shared__ float sDist[EPB], sCcut[EPB], sWl[Hh], sBe1[Hh], sBe2[Hh];
    __shared__ int   sRow[EPB], sCol[EPB];

    int tid  = threadIdx.x;
    int lane = tid & 31;
    int w    = tid >> 5;          // 0..7
    int wm   = w & 1;             // M strip: rows 32*wm..
    int wn   = w >> 1;            // N strip: cols 64*wn..
    int e0   = blockIdx.x * EPB;

    uint32_t sBu[2];
    sBu[0] = (uint32_t)__cvta_generic_to_shared(Bs[0]);
    sBu[1] = (uint32_t)__cvta_generic_to_shared(Bs[1]);

    // kick off B chunk 0 prefetch immediately (overlaps gathers below)
    {
        const uint32_t* src = g_We2tf;     // chunk 0 rows 0..15
        #pragma unroll
        for (int i = 0; i < 4; i++) {
            int idx4 = tid + i * 256;            // 0..1023 float4 index
            int k  = idx4 >> 6;                  // 64 float4 per row
            int n4 = (idx4 & 63) << 2;
            cp_async16(sBu[0] + (k * ASTB + n4) * 4, src + k * Hh + n4);
        }
        asm volatile("cp.async.commit_group;" ::: "memory");
    }

    // per-edge scalars
    if (tid < EPB) {
        int e = e0 + tid;
        int r = eidx[e];
        int c = eidx[Ee + e];
        sRow[tid] = r;
        sCol[tid] = c;
        float dx = x[r * 3 + 0] - x[c * 3 + 0];
        float dy = x[r * 3 + 1] - x[c * 3 + 1];
        float dz = x[r * 3 + 2] - x[c * 3 + 2];
        float d  = sqrtf(dx * dx + dy * dy + dz * dz);
        sDist[tid] = d;
        float cc = 0.5f * (__cosf(d * (kPi / kCutoff)) + 1.0f);
        sCcut[tid] = (d <= kCutoff) ? cc : 0.0f;
        atomicAdd(&g_cnt[c], 1.0f);
    }
    sWl[tid]  = We1[(2 * Cc) * Hh + tid];
    sBe1[tid] = be1[tid];
    sBe2[tid] = be2[tid];
    __syncthreads();   // sRow/sCol/sDist/sWl visible

    // ---- A tile: silu(P1[row] + P2[col] + d*wl + b1) -> tf32
    #pragma unroll 1
    for (int ei = 0; ei < 8; ei++) {
        int e = w * 8 + ei;
        float d = sDist[e];
        const float4* p1 = (const float4*)(g_P1 + sRow[e] * Hh);
        const float4* p2 = (const float4*)(g_P2 + sCol[e] * Hh);
        #pragma unroll
        for (int g = 0; g < 2; g++) {
            int k4 = g * 32 + lane;
            float4 a  = p1[k4];
            float4 b2 = p2[k4];
            float4 wl = ((const float4*)sWl)[k4];
            float4 bb = ((const float4*)sBe1)[k4];
            uint32_t* dst = As + e * ASTA + k4 * 4;
            dst[0] = f2tf32(silu_f(a.x + b2.x + d * wl.x + bb.x));
            dst[1] = f2tf32(silu_f(a.y + b2.y + d * wl.y + bb.y));
            dst[2] = f2tf32(silu_f(a.z + b2.z + d * wl.z + bb.z));
            dst[3] = f2tf32(silu_f(a.w + b2.w + d * wl.w + bb.w));
        }
    }
    asm volatile("cp.async.wait_group 0;" ::: "memory");
    __syncthreads();

    // ---- mainloop: 16 K-chunks of 16, double-buffered B via cp.async
    float acc[2][8][4];
    #pragma unroll
    for (int mt = 0; mt < 2; mt++)
        #pragma unroll
        for (int nt = 0; nt < 8; nt++)
            #pragma unroll
            for (int q = 0; q < 4; q++) acc[mt][nt][q] = 0.0f;

    int ar0 = 32 * wm + (lane >> 2);
    int bc0 = 64 * wn + (lane >> 2);
    const uint32_t* Aw = As + ar0 * ASTA + (lane & 3);

    #pragma unroll 1
    for (int kc = 0; kc < 16; kc++) {
        if (kc < 15) {
            const uint32_t* src = g_We2tf + (kc + 1) * KC * Hh;
            uint32_t dstb = sBu[(kc + 1) & 1];
            #pragma unroll
            for (int i = 0; i < 4; i++) {
                int idx4 = tid + i * 256;
                int k  = idx4 >> 6;
                int n4 = (idx4 & 63) << 2;
                cp_async16(dstb + (k * ASTB + n4) * 4, src + k * Hh + n4);
            }
            asm volatile("cp.async.commit_group;" ::: "memory");
        }
        const uint32_t* Bw = Bs[kc & 1] + (lane & 3) * ASTB + bc0;
        #pragma unroll
        for (int st = 0; st < 2; st++) {
            const uint32_t* Ab0 = Aw + kc * KC + st * 8;
            const uint32_t* Bb  = Bw + st * 8 * ASTB;
            uint32_t a[2][4];
            #pragma unroll
            for (int mt = 0; mt < 2; mt++) {
                const uint32_t* Ab = Ab0 + mt * 16 * ASTA;
                a[mt][0] = Ab[0];
                a[mt][1] = Ab[8 * ASTA];
                a[mt][2] = Ab[4];
                a[mt][3] = Ab[8 * ASTA + 4];
            }
            uint32_t b[8][2];
            #pragma unroll
            for (int nt = 0; nt < 8; nt++) {
                b[nt][0] = Bb[8 * nt];
                b[nt][1] = Bb[4 * ASTB + 8 * nt];
            }
            #pragma unroll
            for (int mt = 0; mt < 2; mt++)
                #pragma unroll
                for (int nt = 0; nt < 8; nt++)
                    mma_tf32(acc[mt][nt][0], acc[mt][nt][1],
                             acc[mt][nt][2], acc[mt][nt][3],
                             a[mt][0], a[mt][1], a[mt][2], a[mt][3],
                             b[nt][0], b[nt][1]);
        }
        if (kc < 15) asm volatile("cp.async.wait_group 0;" ::: "memory");
        __syncthreads();
    }

    // ---- epilogue: +bias, silu, *cutoff, scatter-add
    #pragma unroll
    for (int mt = 0; mt < 2; mt++) {
        int r0 = 32 * wm + 16 * mt + (lane >> 2);   // edge row for c0/c1
        int r1 = r0 + 8;                            // edge row for c2/c3
        float cc0 = sCcut[r0], cc1 = sCcut[r1];
        int base0 = sCol[r0] * Hh, base1 = sCol[r1] * Hh;
        #pragma unroll
        for (int nt = 0; nt < 8; nt++) {
            int col = 64 * wn + 8 * nt + 2 * (lane & 3);
            float b0 = sBe2[col], b1 = sBe2[col + 1];
            atomicAdd(&g_sums[base0 + col],     silu_f(acc[mt][nt][0] + b0) * cc0);
            atomicAdd(&g_sums[base0 + col + 1], silu_f(acc[mt][nt][1] + b1) * cc0);
            atomicAdd(&g_sums[base1 + col],     silu_f(acc[mt][nt][2] + b0) * cc1);
            atomicAdd(&g_sums[base1 + col + 1], silu_f(acc[mt][nt][3] + b1) * cc1);
        }
    }
}

// ---------------- node MLP layer 1: t = silu([hn, m_aggr] @ Wn1 + bn1) ----------------
__global__ void __launch_bounds__(256) nmlp1_kernel(const float* __restrict__ Wn1,
                                                    const float* __restrict__ bn1) {
    __shared__ float sIn[NB][Cc + Hh];   // [8][384]
    __shared__ float sInv[NB];
    int tid = threadIdx.x;
    int n0  = blockIdx.x * NB;
    if (tid < NB) sInv[tid] = 1.0f / fmaxf(g_cnt[n0 + tid], 1.0f);
    __syncthreads();
    for (int idx = tid; idx < NB * (Cc + Hh); idx += 256) {
        int p = idx / (Cc + Hh);
        int k = idx - p * (Cc + Hh);
        int n = n0 + p;
        float v = (k < Cc) ? g_hn[n * Cc + k]
                           : g_sums[n * Hh + (k - Cc)] * sInv[p];
        sIn[p][k] = v;
    }
    __syncthreads();
    float acc[NB];
    #pragma unroll
    for (int p = 0; p < NB; p++) acc[p] = bn1[tid];
    for (int k = 0; k < Cc + Hh; k++) {
        float wv = Wn1[k * Hh + tid];
        #pragma unroll
        for (int p = 0; p < NB; p++) acc[p] += sIn[p][k] * wv;
    }
    #pragma unroll
    for (int p = 0; p < NB; p++)
        g_t[(n0 + p) * Hh + tid] = silu_f(acc[p]);
}

// ---------------- node MLP layer 2 + residuals ----------------
__global__ void __launch_bounds__(128) nmlp2_kernel(const float* __restrict__ h,
                                                    const float* __restrict__ Wn2,
                                                    const float* __restrict__ bn2) {
    __shared__ float sT[NB][Hh];
    int tid = threadIdx.x;
    int n0  = blockIdx.x * NB;
    for (int idx = tid; idx < NB * Hh; idx += 128)
        sT[idx >> 8][idx & 255] = g_t[n0 * Hh + idx];
    __syncthreads();
    float acc[NB];
    #pragma unroll
    for (int p = 0; p < NB; p++) acc[p] = bn2[tid];
    for (int k = 0; k < Hh; k++) {
        float wv = Wn2[k * Cc + tid];
        #pragma unroll
        for (int p = 0; p < NB; p++) acc[p] += sT[p][k] * wv;
    }
    #pragma unroll
    for (int p = 0; p < NB; p++) {
        int n = n0 + p;
        g_h1[n * Cc + tid] = h[n * Cc + tid] + g_hn[n * Cc + tid] + acc[p];
    }
}

// ---------------- out MLP layer 1 ----------------
__global__ void __launch_bounds__(256) mmlp1_kernel(const float* __restrict__ Wm1,
                                                    const float* __restrict__ bm1) {
    __shared__ float sIn[NB][Cc];
    int tid = threadIdx.x;
    int n0  = blockIdx.x * NB;
    for (int idx = tid; idx < NB * Cc; idx += 256)
        sIn[idx >> 7][idx & 127] = g_h2[n0 * Cc + idx];
    __syncthreads();
    float acc[NB];
    #pragma unroll
    for (int p = 0; p < NB; p++) acc[p] = bm1[tid];
    for (int k = 0; k < Cc; k++) {
        float wv = Wm1[k * Hh + tid];
        #pragma unroll
        for (int p = 0; p < NB; p++) acc[p] += sIn[p][k] * wv;
    }
    #pragma unroll
    for (int p = 0; p < NB; p++)
        g_u[(n0 + p) * Hh + tid] = silu_f(acc[p]);
}

// ---------------- out MLP layer 2 + final residual ----------------
__global__ void __launch_bounds__(128) mmlp2_kernel(const float* __restrict__ Wm2,
                                                    const float* __restrict__ bm2,
                                                    float* __restrict__ out) {
    __shared__ float sU[NB][Hh];
    int tid = threadIdx.x;
    int n0  = blockIdx.x * NB;
    for (int idx = tid; idx < NB * Hh; idx += 128)
        sU[idx >> 8][idx & 255] = g_u[n0 * Hh + idx];
    __syncthreads();
    float acc[NB];
    #pragma unroll
    for (int p = 0; p < NB; p++) acc[p] = bm2[tid];
    for (int k = 0; k < Hh; k++) {
        float wv = Wm2[k * Cc + tid];
        #pragma unroll
        for (int p = 0; p < NB; p++) acc[p] += sU[p][k] * wv;
    }
    #pragma unroll
    for (int p = 0; p < NB; p++) {
        int n = n0 + p;
        out[n * Cc + tid] = g_h1[n * Cc + tid] + acc[p];
    }
}

// ---------------- launch ----------------
extern "C" void kernel_launch(void* const* d_in, const int* in_sizes, int n_in,
                              void* d_out, int out_size) {
    const float* x     = (const float*)d_in[0];
    const float* h     = (const float*)d_in[1];
    const int*   eidx  = (const int*)  d_in[2];
    const float* We1   = (const float*)d_in[3];
    const float* be1   = (const float*)d_in[4];
    const float* We2   = (const float*)d_in[5];
    const float* be2   = (const float*)d_in[6];
    const float* Wn1   = (const float*)d_in[7];
    const float* bn1   = (const float*)d_in[8];
    const float* Wn2   = (const float*)d_in[9];
    const float* bn2   = (const float*)d_in[10];
    const float* Wm1   = (const float*)d_in[11];
    const float* bm1   = (const float*)d_in[12];
    const float* Wm2   = (const float*)d_in[13];
    const float* bm2   = (const float*)d_in[14];
    const float* g1    = (const float*)d_in[15];
    const float* beta1 = (const float*)d_in[16];
    const float* g2    = (const float*)d_in[17];
    const float* beta2 = (const float*)d_in[18];

    static int attr_done = 0;
    if (!attr_done) {
        cudaFuncSetAttribute(edge_kernel,
                             cudaFuncAttributeMaxDynamicSharedMemorySize, EDGE_DSMEM);
        attr_done = 1;
    }

    zero_kernel<<<(Nn * Hh + 1023) / 1024, 1024>>>();
    prepWe2_kernel<<<64, 1024>>>(We2);
    ln1_kernel<<<Nn, Cc>>>(h, g1, beta1);
    p1p2_kernel<<<Nn / NB, 256>>>(We1);
    edge_kernel<<<Ee / EPB, 256, EDGE_DSMEM>>>(x, eidx, We1, be1, be2);
    nmlp1_kernel<<<Nn / NB, 256>>>(Wn1, bn1);
    nmlp2_kernel<<<Nn / NB, 128>>>(h, Wn2, bn2);
    ln2_kernel<<<Nn, Cc>>>(g2, beta2);
    mmlp1_kernel<<<Nn / NB, 256>>>(Wm1, bm1);
    mmlp2_kernel<<<Nn / NB, 128>>>(Wm2, bm2, (float*)d_out);
}

// round 9
// speedup vs baseline: 1.8073x; 1.0073x over previous
#include <cuda_runtime.h>
#include <cstdint>

#define Nn 10000
#define Cc 128
#define Hh 256
#define Ee 320000

constexpr float kCutoff = 5.0f;
constexpr float kEps    = 1e-5f;
constexpr float kPi     = 3.14159265358979323846f;

// ---------------- scratch (device globals; no runtime allocation) ----------------
__device__ float g_hn  [Nn * Cc];   // LN1(h)
__device__ float g_P1  [Nn * Hh];   // hn @ We1[0:128]
__device__ float g_P2  [Nn * Hh];   // hn @ We1[128:256]
__device__ float g_sums[Nn * Hh];   // segment sums
__device__ float g_cnt [Nn];        // segment counts
__device__ float g_t   [Nn * Hh];   // node MLP hidden
__device__ float g_h1  [Nn * Cc];
__device__ float g_h2  [Nn * Cc];   // LN2(h1)
__device__ float g_u   [Nn * Hh];   // out MLP hidden
__device__ uint32_t g_We2tf[Hh * Hh];  // We2 pre-converted to tf32 (rna), row-major [k][n]

__device__ __forceinline__ float silu_f(float v) {
    return v * (1.0f / (1.0f + __expf(-v)));
}
__device__ __forceinline__ uint32_t f2tf32(float f) {
    uint32_t r; asm("cvt.rna.tf32.f32 %0, %1;" : "=r"(r) : "f"(f)); return r;
}
__device__ __forceinline__ void cp_async16(uint32_t dst, const void* src) {
    asm volatile("cp.async.ca.shared.global [%0], [%1], 16;"
                 :: "r"(dst), "l"(src) : "memory");
}
// tf32 m16n8k8 mma.sync
__device__ __forceinline__ void mma_tf32(float& c0, float& c1, float& c2, float& c3,
                                         uint32_t a0, uint32_t a1, uint32_t a2, uint32_t a3,
                                         uint32_t b0, uint32_t b1) {
    asm volatile(
        "mma.sync.aligned.m16n8k8.row.col.f32.tf32.tf32.f32 "
        "{%0,%1,%2,%3}, {%4,%5,%6,%7}, {%8,%9}, {%0,%1,%2,%3};"
        : "+f"(c0), "+f"(c1), "+f"(c2), "+f"(c3)
        : "r"(a0), "r"(a1), "r"(a2), "r"(a3), "r"(b0), "r"(b1));
}

// ---------------- zero the accumulators (graph replays must reset) ----------------
__global__ void zero_kernel() {
    int i = blockIdx.x * blockDim.x + threadIdx.x;
    if (i < Nn * Hh) g_sums[i] = 0.0f;
    if (i < Nn)      g_cnt[i]  = 0.0f;
}

// ---------------- We2 -> tf32 (rna) once ----------------
__global__ void prepWe2_kernel(const float* __restrict__ We2) {
    int i = blockIdx.x * 1024 + threadIdx.x;
    if (i < Hh * Hh) g_We2tf[i] = f2tf32(We2[i]);
}

// ---------------- LayerNorm over C=128, one block per row ----------------
__device__ __forceinline__ void ln_row(const float* __restrict__ in,
                                       const float* __restrict__ gg,
                                       const float* __restrict__ bb,
                                       float* __restrict__ out) {
    int n = blockIdx.x, c = threadIdx.x;
    float v = in[n * Cc + c];
    float s = v, s2 = v * v;
    #pragma unroll
    for (int o = 16; o; o >>= 1) {
        s  += __shfl_xor_sync(0xffffffffu, s,  o);
        s2 += __shfl_xor_sync(0xffffffffu, s2, o);
    }
    __shared__ float ws[4], ws2[4];
    if ((c & 31) == 0) { ws[c >> 5] = s; ws2[c >> 5] = s2; }
    __syncthreads();
    s  = ws[0]  + ws[1]  + ws[2]  + ws[3];
    s2 = ws2[0] + ws2[1] + ws2[2] + ws2[3];
    float mu  = s * (1.0f / Cc);
    float var = s2 * (1.0f / Cc) - mu * mu;
    out[n * Cc + c] = (v - mu) * rsqrtf(var + kEps) * gg[c] + bb[c];
}

__global__ void ln1_kernel(const float* __restrict__ h,
                           const float* __restrict__ g1,
                           const float* __restrict__ b1) {
    ln_row(h, g1, b1, g_hn);
}
__global__ void ln2_kernel(const float* __restrict__ g2,
                           const float* __restrict__ b2) {
    ln_row(g_h1, g2, b2, g_h2);
}

// ---------------- node projections P1/P2 = hn @ We1 halves ----------------
#define NB 8
__global__ void __launch_bounds__(256) p1p2_kernel(const float* __restrict__ We1) {
    __shared__ float sIn[NB][Cc];
    int tid = threadIdx.x;
    int n0  = blockIdx.x * NB;
    for (int idx = tid; idx < NB * Cc; idx += 256)
        sIn[idx >> 7][idx & 127] = g_hn[n0 * Cc + idx];
    __syncthreads();
    float a1[NB], a2[NB];
    #pragma unroll
    for (int p = 0; p < NB; p++) { a1[p] = 0.f; a2[p] = 0.f; }
    for (int k = 0; k < Cc; k++) {
        float w1 = We1[k * Hh + tid];
        float w2 = We1[(k + Cc) * Hh + tid];
        #pragma unroll
        for (int p = 0; p < NB; p++) {
            float v = sIn[p][k];
            a1[p] += v * w1;
            a2[p] += v * w2;
        }
    }
    #pragma unroll
    for (int p = 0; p < NB; p++) {
        g_P1[(n0 + p) * Hh + tid] = a1[p];
        g_P2[(n0 + p) * Hh + tid] = a2[p];
    }
}

// ---------------- edge kernel: layer1 gather -> tf32 mma.sync GEMM -> silu*cutoff -> scatter ----
#define EPB  64                 // edges per CTA (GEMM M)
#define KC   16                 // K-chunk rows
#define ASTA 260                // A smem row stride (floats): banks 4r+c conflict-free
#define ASTB 264                // B smem row stride (floats): banks 8r+c conflict-free
constexpr int A_SMEM_U32 = EPB * ASTA;       // 16640 u32
constexpr int B_SMEM_U32 = KC * ASTB;        // 4224 u32 each
constexpr int EDGE_DSMEM = (A_SMEM_U32 + 2 * B_SMEM_U32) * 4;   // 100352 B

__global__ void __launch_bounds__(256, 2) edge_kernel(const float* __restrict__ x,
                                                      const int*   __restrict__ eidx,
                                                      const float* __restrict__ We1,
                                                      const float* __restrict__ be1,
                                                      const float* __restrict__ be2) {
    extern __shared__ __align__(16) uint32_t dynbuf[];
    uint32_t* As = dynbuf;                       // [64][ASTA] tf32
    uint32_t* Bs[2] = { dynbuf + A_SMEM_U32,
                        dynbuf + A_SMEM_U32 + B_SMEM_U32 };

    __shared__ float sDist[EPB], sCcut[EPB], sWl[Hh], sBe1[Hh], sBe2[Hh];
    __shared__ int   sRow[EPB], sCol[EPB];

    int tid  = threadIdx.x;
    int lane = tid & 31;
    int w    = tid >> 5;          // 0..7
    int wm   = w & 1;             // M strip: rows 32*wm..
    int wn   = w >> 1;            // N strip: cols 64*wn..
    int e0   = blockIdx.x * EPB;

    uint32_t sBu[2];
    sBu[0] = (uint32_t)__cvta_generic_to_shared(Bs[0]);
    sBu[1] = (uint32_t)__cvta_generic_to_shared(Bs[1]);

    // kick off B chunk 0 prefetch immediately (overlaps gathers below)
    {
        const uint32_t* src = g_We2tf;     // chunk 0 rows 0..15
        #pragma unroll
        for (int i = 0; i < 4; i++) {
            int idx4 = tid + i * 256;            // 0..1023 float4 index
            int k  = idx4 >> 6;                  // 64 float4 per row
            int n4 = (idx4 & 63) << 2;
            cp_async16(sBu[0] + (k * ASTB + n4) * 4, src + k * Hh + n4);
        }
        asm volatile("cp.async.commit_group;" ::: "memory");
    }

    // per-edge scalars
    if (tid < EPB) {
        int e = e0 + tid;
        int r = eidx[e];
        int c = eidx[Ee + e];
        sRow[tid] = r;
        sCol[tid] = c;
        float dx = x[r * 3 + 0] - x[c * 3 + 0];
        float dy = x[r * 3 + 1] - x[c * 3 + 1];
        float dz = x[r * 3 + 2] - x[c * 3 + 2];
        float d  = sqrtf(dx * dx + dy * dy + dz * dz);
        sDist[tid] = d;
        float cc = 0.5f * (__cosf(d * (kPi / kCutoff)) + 1.0f);
        sCcut[tid] = (d <= kCutoff) ? cc : 0.0f;
        atomicAdd(&g_cnt[c], 1.0f);
    }
    sWl[tid]  = We1[(2 * Cc) * Hh + tid];
    sBe1[tid] = be1[tid];
    sBe2[tid] = be2[tid];
    __syncthreads();   // sRow/sCol/sDist/sWl visible

    // ---- A tile: silu(P1[row] + P2[col] + d*wl + b1) -> tf32
    #pragma unroll 1
    for (int ei = 0; ei < 8; ei++) {
        int e = w * 8 + ei;
        float d = sDist[e];
        const float4* p1 = (const float4*)(g_P1 + sRow[e] * Hh);
        const float4* p2 = (const float4*)(g_P2 + sCol[e] * Hh);
        #pragma unroll
        for (int g = 0; g < 2; g++) {
            int k4 = g * 32 + lane;
            float4 a  = p1[k4];
            float4 b2 = p2[k4];
            float4 wl = ((const float4*)sWl)[k4];
            float4 bb = ((const float4*)sBe1)[k4];
            uint32_t* dst = As + e * ASTA + k4 * 4;
            dst[0] = f2tf32(silu_f(a.x + b2.x + d * wl.x + bb.x));
            dst[1] = f2tf32(silu_f(a.y + b2.y + d * wl.y + bb.y));
            dst[2] = f2tf32(silu_f(a.z + b2.z + d * wl.z + bb.z));
            dst[3] = f2tf32(silu_f(a.w + b2.w + d * wl.w + bb.w));
        }
    }
    asm volatile("cp.async.wait_group 0;" ::: "memory");
    __syncthreads();

    // ---- mainloop: 16 K-chunks of 16, double-buffered B via cp.async
    float acc[2][8][4];
    #pragma unroll
    for (int mt = 0; mt < 2; mt++)
        #pragma unroll
        for (int nt = 0; nt < 8; nt++)
            #pragma unroll
            for (int q = 0; q < 4; q++) acc[mt][nt][q] = 0.0f;

    int ar0 = 32 * wm + (lane >> 2);
    int bc0 = 64 * wn + (lane >> 2);
    const uint32_t* Aw = As + ar0 * ASTA + (lane & 3);

    #pragma unroll 1
    for (int kc = 0; kc < 16; kc++) {
        if (kc < 15) {
            const uint32_t* src = g_We2tf + (kc + 1) * KC * Hh;
            uint32_t dstb = sBu[(kc + 1) & 1];
            #pragma unroll
            for (int i = 0; i < 4; i++) {
                int idx4 = tid + i * 256;
                int k  = idx4 >> 6;
                int n4 = (idx4 & 63) << 2;
                cp_async16(dstb + (k * ASTB + n4) * 4, src + k * Hh + n4);
            }
            asm volatile("cp.async.commit_group;" ::: "memory");
        }
        const uint32_t* Bw = Bs[kc & 1] + (lane & 3) * ASTB + bc0;
        #pragma unroll
        for (int st = 0; st < 2; st++) {
            const uint32_t* Ab0 = Aw + kc * KC + st * 8;
            const uint32_t* Bb  = Bw + st * 8 * ASTB;
            uint32_t a[2][4];
            #pragma unroll
            for (int mt = 0; mt < 2; mt++) {
                const uint32_t* Ab = Ab0 + mt * 16 * ASTA;
                a[mt][0] = Ab[0];
                a[mt][1] = Ab[8 * ASTA];
                a[mt][2] = Ab[4];
                a[mt][3] = Ab[8 * ASTA + 4];
            }
            uint32_t b[8][2];
            #pragma unroll
            for (int nt = 0; nt < 8; nt++) {
                b[nt][0] = Bb[8 * nt];
                b[nt][1] = Bb[4 * ASTB + 8 * nt];
            }
            #pragma unroll
            for (int mt = 0; mt < 2; mt++)
                #pragma unroll
                for (int nt = 0; nt < 8; nt++)
                    mma_tf32(acc[mt][nt][0], acc[mt][nt][1],
                             acc[mt][nt][2], acc[mt][nt][3],
                             a[mt][0], a[mt][1], a[mt][2], a[mt][3],
                             b[nt][0], b[nt][1]);
        }
        if (kc < 15) asm volatile("cp.async.wait_group 0;" ::: "memory");
        __syncthreads();
    }

    // ---- epilogue: +bias, silu, *cutoff, scatter-add
    #pragma unroll
    for (int mt = 0; mt < 2; mt++) {
        int r0 = 32 * wm + 16 * mt + (lane >> 2);   // edge row for c0/c1
        int r1 = r0 + 8;                            // edge row for c2/c3
        float cc0 = sCcut[r0], cc1 = sCcut[r1];
        int base0 = sCol[r0] * Hh, base1 = sCol[r1] * Hh;
        #pragma unroll
        for (int nt = 0; nt < 8; nt++) {
            int col = 64 * wn + 8 * nt + 2 * (lane & 3);
            float b0 = sBe2[col], b1 = sBe2[col + 1];
            atomicAdd(&g_sums[base0 + col],     silu_f(acc[mt][nt][0] + b0) * cc0);
            atomicAdd(&g_sums[base0 + col + 1], silu_f(acc[mt][nt][1] + b1) * cc0);
            atomicAdd(&g_sums[base1 + col],     silu_f(acc[mt][nt][2] + b0) * cc1);
            atomicAdd(&g_sums[base1 + col + 1], silu_f(acc[mt][nt][3] + b1) * cc1);
        }
    }
}

// ---------------- node MLP layer 1: t = silu([hn, m_aggr] @ Wn1 + bn1) ----------------
__global__ void __launch_bounds__(256) nmlp1_kernel(const float* __restrict__ Wn1,
                                                    const float* __restrict__ bn1) {
    __shared__ float sIn[NB][Cc + Hh];   // [8][384]
    __shared__ float sInv[NB];
    int tid = threadIdx.x;
    int n0  = blockIdx.x * NB;
    if (tid < NB) sInv[tid] = 1.0f / fmaxf(g_cnt[n0 + tid], 1.0f);
    __syncthreads();
    for (int idx = tid; idx < NB * (Cc + Hh); idx += 256) {
        int p = idx / (Cc + Hh);
        int k = idx - p * (Cc + Hh);
        int n = n0 + p;
        float v = (k < Cc) ? g_hn[n * Cc + k]
                           : g_sums[n * Hh + (k - Cc)] * sInv[p];
        sIn[p][k] = v;
    }
    __syncthreads();
    float acc[NB];
    #pragma unroll
    for (int p = 0; p < NB; p++) acc[p] = bn1[tid];
    for (int k = 0; k < Cc + Hh; k++) {
        float wv = Wn1[k * Hh + tid];
        #pragma unroll
        for (int p = 0; p < NB; p++) acc[p] += sIn[p][k] * wv;
    }
    #pragma unroll
    for (int p = 0; p < NB; p++)
        g_t[(n0 + p) * Hh + tid] = silu_f(acc[p]);
}

// ---------------- node MLP layer 2 + residuals ----------------
__global__ void __launch_bounds__(128) nmlp2_kernel(const float* __restrict__ h,
                                                    const float* __restrict__ Wn2,
                                                    const float* __restrict__ bn2) {
    __shared__ float sT[NB][Hh];
    int tid = threadIdx.x;
    int n0  = blockIdx.x * NB;
    for (int idx = tid; idx < NB * Hh; idx += 128)
        sT[idx >> 8][idx & 255] = g_t[n0 * Hh + idx];
    __syncthreads();
    float acc[NB];
    #pragma unroll
    for (int p = 0; p < NB; p++) acc[p] = bn2[tid];
    for (int k = 0; k < Hh; k++) {
        float wv = Wn2[k * Cc + tid];
        #pragma unroll
        for (int p = 0; p < NB; p++) acc[p] += sT[p][k] * wv;
    }
    #pragma unroll
    for (int p = 0; p < NB; p++) {
        int n = n0 + p;
        g_h1[n * Cc + tid] = h[n * Cc + tid] + g_hn[n * Cc + tid] + acc[p];
    }
}

// ---------------- out MLP layer 1 ----------------
__global__ void __launch_bounds__(256) mmlp1_kernel(const float* __restrict__ Wm1,
                                                    const float* __restrict__ bm1) {
    __shared__ float sIn[NB][Cc];
    int tid = threadIdx.x;
    int n0  = blockIdx.x * NB;
    for (int idx = tid; idx < NB * Cc; idx += 256)
        sIn[idx >> 7][idx & 127] = g_h2[n0 * Cc + idx];
    __syncthreads();
    float acc[NB];
    #pragma unroll
    for (int p = 0; p < NB; p++) acc[p] = bm1[tid];
    for (int k = 0; k < Cc; k++) {
        float wv = Wm1[k * Hh + tid];
        #pragma unroll
        for (int p = 0; p < NB; p++) acc[p] += sIn[p][k] * wv;
    }
    #pragma unroll
    for (int p = 0; p < NB; p++)
        g_u[(n0 + p) * Hh + tid] = silu_f(acc[p]);
}

// ---------------- out MLP layer 2 + final residual ----------------
__global__ void __launch_bounds__(128) mmlp2_kernel(const float* __restrict__ Wm2,
                                                    const float* __restrict__ bm2,
                                                    float* __restrict__ out) {
    __shared__ float sU[NB][Hh];
    int tid = threadIdx.x;
    int n0  = blockIdx.x * NB;
    for (int idx = tid; idx < NB * Hh; idx += 128)
        sU[idx >> 8][idx & 255] = g_u[n0 * Hh + idx];
    __syncthreads();
    float acc[NB];
    #pragma unroll
    for (int p = 0; p < NB; p++) acc[p] = bm2[tid];
    for (int k = 0; k < Hh; k++) {
        float wv = Wm2[k * Cc + tid];
        #pragma unroll
        for (int p = 0; p < NB; p++) acc[p] += sU[p][k] * wv;
    }
    #pragma unroll
    for (int p = 0; p < NB; p++) {
        int n = n0 + p;
        out[n * Cc + tid] = g_h1[n * Cc + tid] + acc[p];
    }
}

// ---------------- launch ----------------
extern "C" void kernel_launch(void* const* d_in, const int* in_sizes, int n_in,
                              void* d_out, int out_size) {
    const float* x     = (const float*)d_in[0];
    const float* h     = (const float*)d_in[1];
    const int*   eidx  = (const int*)  d_in[2];
    const float* We1   = (const float*)d_in[3];
    const float* be1   = (const float*)d_in[4];
    const float* We2   = (const float*)d_in[5];
    const float* be2   = (const float*)d_in[6];
    const float* Wn1   = (const float*)d_in[7];
    const float* bn1   = (const float*)d_in[8];
    const float* Wn2   = (const float*)d_in[9];
    const float* bn2   = (const float*)d_in[10];
    const float* Wm1   = (const float*)d_in[11];
    const float* bm1   = (const float*)d_in[12];
    const float* Wm2   = (const float*)d_in[13];
    const float* bm2   = (const float*)d_in[14];
    const float* g1    = (const float*)d_in[15];
    const float* beta1 = (const float*)d_in[16];
    const float* g2    = (const float*)d_in[17];
    const float* beta2 = (const float*)d_in[18];

    static int attr_done = 0;
    if (!attr_done) {
        cudaFuncSetAttribute(edge_kernel,
                             cudaFuncAttributeMaxDynamicSharedMemorySize, EDGE_DSMEM);
        attr_done = 1;
    }

    zero_kernel<<<(Nn * Hh + 1023) / 1024, 1024>>>();
    prepWe2_kernel<<<64, 1024>>>(We2);
    ln1_kernel<<<Nn, Cc>>>(h, g1, beta1);
    p1p2_kernel<<<Nn / NB, 256>>>(We1);
    edge_kernel<<<Ee / EPB, 256, EDGE_DSMEM>>>(x, eidx, We1, be1, be2);
    nmlp1_kernel<<<Nn / NB, 256>>>(Wn1, bn1);
    nmlp2_kernel<<<Nn / NB, 128>>>(h, Wn2, bn2);
    ln2_kernel<<<Nn, Cc>>>(g2, beta2);
    mmlp1_kernel<<<Nn / NB, 256>>>(Wm1, bm1);
    mmlp2_kernel<<<Nn / NB, 128>>>(Wm2, bm2, (float*)d_out);
}

// round 10
// speedup vs baseline: 1.9052x; 1.0542x over previous
#include <cuda_runtime.h>
#include <cstdint>

#define Nn 10000
#define Cc 128
#define Hh 256
#define Ee 320000

constexpr float kCutoff = 5.0f;
constexpr float kEps    = 1e-5f;
constexpr float kPi     = 3.14159265358979323846f;

// ---------------- scratch (device globals; no runtime allocation) ----------------
__device__ float    g_hn   [Nn * Cc];    // LN1(h) exact (residual path)
__device__ uint32_t g_hn_tf[Nn * Cc];    // LN1(h) tf32 (GEMM A)
__device__ float    g_P12  [Nn * 512];   // [P1 | P2] node projections
__device__ float    g_sums [Nn * Hh];    // segment sums
__device__ float    g_cnt  [Nn];         // segment counts
__device__ uint32_t g_ma_tf[Nn * Hh];    // m_aggr tf32
__device__ uint32_t g_t    [Nn * Hh];    // node MLP hidden (tf32)
__device__ float    g_h1   [Nn * Cc];
__device__ uint32_t g_h2_tf[Nn * Cc];    // LN2(h1) tf32
__device__ uint32_t g_u    [Nn * Hh];    // out MLP hidden (tf32)
// tf32 weights
__device__ uint32_t g_We2tf[Hh * Hh];        // [k][n] 256x256
__device__ uint32_t g_We1tf[Cc * 512];       // [k][n'] n'<256: We1[k][n'], else We1[k+128][n'-256]
__device__ uint32_t g_Wn1tf[(Cc + Hh) * Hh]; // 384x256
__device__ uint32_t g_Wn2tf[Hh * Cc];        // 256x128
__device__ uint32_t g_Wm1tf[Cc * Hh];        // 128x256
__device__ uint32_t g_Wm2tf[Hh * Cc];        // 256x128

__device__ __forceinline__ float silu_f(float v) {
    return v * (1.0f / (1.0f + __expf(-v)));
}
__device__ __forceinline__ uint32_t f2tf32(float f) {
    uint32_t r; asm("cvt.rna.tf32.f32 %0, %1;" : "=r"(r) : "f"(f)); return r;
}
__device__ __forceinline__ void cp_async16(uint32_t dst, const void* src) {
    asm volatile("cp.async.ca.shared.global [%0], [%1], 16;"
                 :: "r"(dst), "l"(src) : "memory");
}
__device__ __forceinline__ void mma_tf32(float& c0, float& c1, float& c2, float& c3,
                                         uint32_t a0, uint32_t a1, uint32_t a2, uint32_t a3,
                                         uint32_t b0, uint32_t b1) {
    asm volatile(
        "mma.sync.aligned.m16n8k8.row.col.f32.tf32.tf32.f32 "
        "{%0,%1,%2,%3}, {%4,%5,%6,%7}, {%8,%9}, {%0,%1,%2,%3};"
        : "+f"(c0), "+f"(c1), "+f"(c2), "+f"(c3)
        : "r"(a0), "r"(a1), "r"(a2), "r"(a3), "r"(b0), "r"(b1));
}

// ---------------- zero the accumulators (graph replays must reset) ----------------
__global__ void zero_kernel() {
    int i = blockIdx.x * blockDim.x + threadIdx.x;
    if (i < Nn * Hh) g_sums[i] = 0.0f;
    if (i < Nn)      g_cnt[i]  = 0.0f;
}

// ---------------- weights -> tf32 once ----------------
__global__ void prepW_kernel(const float* __restrict__ We2, const float* __restrict__ Wn1,
                             const float* __restrict__ Wn2, const float* __restrict__ Wm1,
                             const float* __restrict__ Wm2, const float* __restrict__ We1) {
    int i = blockIdx.x * 256 + threadIdx.x;        // 0 .. 98303
    if (i < Hh * Hh) g_We2tf[i] = f2tf32(We2[i]);
    if (i < (Cc + Hh) * Hh) g_Wn1tf[i] = f2tf32(Wn1[i]);
    if (i < Hh * Cc) {
        g_Wn2tf[i] = f2tf32(Wn2[i]);
        g_Wm1tf[i] = f2tf32(Wm1[i]);
        g_Wm2tf[i] = f2tf32(Wm2[i]);
    }
    if (i < Cc * 512) {
        int k = i >> 9, n = i & 511;
        float v = (n < 256) ? We1[k * Hh + n] : We1[(k + 128) * Hh + (n - 256)];
        g_We1tf[i] = f2tf32(v);
    }
}

// ---------------- LayerNorm over C=128, one block per row ----------------
template<int WHICH>   // 0: h -> g_hn + g_hn_tf ; 1: g_h1 -> g_h2_tf
__global__ void ln_kernel(const float* __restrict__ in,
                          const float* __restrict__ gg,
                          const float* __restrict__ bb) {
    int n = blockIdx.x, c = threadIdx.x;
    const float* src = (WHICH == 0) ? in : g_h1;
    float v = src[n * Cc + c];
    float s = v, s2 = v * v;
    #pragma unroll
    for (int o = 16; o; o >>= 1) {
        s  += __shfl_xor_sync(0xffffffffu, s,  o);
        s2 += __shfl_xor_sync(0xffffffffu, s2, o);
    }
    __shared__ float ws[4], ws2[4];
    if ((c & 31) == 0) { ws[c >> 5] = s; ws2[c >> 5] = s2; }
    __syncthreads();
    s  = ws[0]  + ws[1]  + ws[2]  + ws[3];
    s2 = ws2[0] + ws2[1] + ws2[2] + ws2[3];
    float mu  = s * (1.0f / Cc);
    float var = s2 * (1.0f / Cc) - mu * mu;
    float o = (v - mu) * rsqrtf(var + kEps) * gg[c] + bb[c];
    if (WHICH == 0) {
        g_hn[n * Cc + c]    = o;
        g_hn_tf[n * Cc + c] = f2tf32(o);
    } else {
        g_h2_tf[n * Cc + c] = f2tf32(o);
    }
}

// ---------------- m_aggr -> tf32 ----------------
__global__ void magg_kernel() {
    int n = blockIdx.x, k = threadIdx.x;
    float inv = 1.0f / fmaxf(g_cnt[n], 1.0f);
    g_ma_tf[n * Hh + k] = f2tf32(g_sums[n * Hh + k] * inv);
}

// ---------------- generic node GEMM on mma.sync tf32 ----------------
enum { M_P1P2 = 0, M_NMLP1 = 1, M_NMLP2 = 2, M_MMLP1 = 3, M_MMLP2 = 4 };
#define BSTN 136   // B smem row stride (u32): 136 mod 32 == 8 -> conflict-free frag reads

template<int K, int NCOLS, int MODE>
__global__ void __launch_bounds__(256) node_gemm(const float* __restrict__ bias,
                                                 const float* __restrict__ res1,
                                                 float* __restrict__ out_h) {
    const uint32_t* A0;  const uint32_t* A1 = nullptr;
    const uint32_t* Btf; float* outf = nullptr; uint32_t* outu = nullptr;
    if constexpr (MODE == M_P1P2)  { A0 = g_hn_tf; Btf = g_We1tf; outf = g_P12; }
    if constexpr (MODE == M_NMLP1) { A0 = g_hn_tf; A1 = g_ma_tf; Btf = g_Wn1tf; outu = g_t; }
    if constexpr (MODE == M_NMLP2) { A0 = g_t;     Btf = g_Wn2tf; outf = g_h1; }
    if constexpr (MODE == M_MMLP1) { A0 = g_h2_tf; Btf = g_Wm1tf; outu = g_u; }
    if constexpr (MODE == M_MMLP2) { A0 = g_u;     Btf = g_Wm2tf; outf = out_h; }
    constexpr int KA0 = (MODE == M_NMLP1) ? 128 : K;
    constexpr int NCH = K / 16;

    __shared__ __align__(16) uint32_t Bs[2][16 * BSTN];
    int tid = threadIdx.x, lane = tid & 31, w = tid >> 5;
    int wm = w & 1, wn = w >> 1;
    int rbase = blockIdx.x * 64;
    int cbase = blockIdx.y * 128;
    uint32_t sB[2] = { (uint32_t)__cvta_generic_to_shared(Bs[0]),
                       (uint32_t)__cvta_generic_to_shared(Bs[1]) };

    // prefetch B chunk 0
    #pragma unroll
    for (int i = 0; i < 2; i++) {
        int idx4 = tid + i * 256;
        int k = idx4 >> 5, n4 = (idx4 & 31) << 2;
        cp_async16(sB[0] + (k * BSTN + n4) * 4, Btf + k * NCOLS + cbase + n4);
    }
    asm volatile("cp.async.commit_group;\n\tcp.async.wait_group 0;" ::: "memory");
    __syncthreads();

    float acc[2][4][4];
    #pragma unroll
    for (int mt = 0; mt < 2; mt++)
        #pragma unroll
        for (int nt = 0; nt < 4; nt++)
            #pragma unroll
            for (int q = 0; q < 4; q++) acc[mt][nt][q] = 0.0f;

    // clamped A rows (guard tail block)
    int rc[2][2];
    #pragma unroll
    for (int mt = 0; mt < 2; mt++) {
        rc[mt][0] = min(rbase + 32 * wm + 16 * mt + (lane >> 2), Nn - 1);
        rc[mt][1] = min(rbase + 32 * wm + 16 * mt + (lane >> 2) + 8, Nn - 1);
    }
    int bq = 32 * wn + (lane >> 2);

    #pragma unroll 1
    for (int kc = 0; kc < NCH; kc++) {
        if (kc < NCH - 1) {
            const uint32_t* src = Btf + (kc + 1) * 16 * NCOLS + cbase;
            uint32_t d = sB[(kc + 1) & 1];
            #pragma unroll
            for (int i = 0; i < 2; i++) {
                int idx4 = tid + i * 256;
                int k = idx4 >> 5, n4 = (idx4 & 31) << 2;
                cp_async16(d + (k * BSTN + n4) * 4, src + k * NCOLS + n4);
            }
            asm volatile("cp.async.commit_group;" ::: "memory");
        }
        const uint32_t* Bw = Bs[kc & 1] + (lane & 3) * BSTN + bq;
        #pragma unroll
        for (int st = 0; st < 2; st++) {
            int kk = kc * 16 + st * 8 + (lane & 3);
            uint32_t a[2][4];
            #pragma unroll
            for (int mt = 0; mt < 2; mt++) {
                const uint32_t *pa0, *pa1;
                if (MODE == M_NMLP1 && kk >= 128) {
                    pa0 = A1 + rc[mt][0] * Hh + (kk - 128);
                    pa1 = A1 + rc[mt][1] * Hh + (kk - 128);
                } else {
                    pa0 = A0 + rc[mt][0] * KA0 + kk;
                    pa1 = A0 + rc[mt][1] * KA0 + kk;
                }
                a[mt][0] = pa0[0]; a[mt][1] = pa1[0];
                a[mt][2] = pa0[4]; a[mt][3] = pa1[4];
            }
            uint32_t b[4][2];
            const uint32_t* Bb = Bw + st * 8 * BSTN;
            #pragma unroll
            for (int nt = 0; nt < 4; nt++) {
                b[nt][0] = Bb[8 * nt];
                b[nt][1] = Bb[4 * BSTN + 8 * nt];
            }
            #pragma unroll
            for (int mt = 0; mt < 2; mt++)
                #pragma unroll
                for (int nt = 0; nt < 4; nt++)
                    mma_tf32(acc[mt][nt][0], acc[mt][nt][1], acc[mt][nt][2], acc[mt][nt][3],
                             a[mt][0], a[mt][1], a[mt][2], a[mt][3], b[nt][0], b[nt][1]);
        }
        if (kc < NCH - 1) asm volatile("cp.async.wait_group 0;" ::: "memory");
        __syncthreads();
    }

    // epilogue
    #pragma unroll
    for (int mt = 0; mt < 2; mt++) {
        int r0 = rbase + 32 * wm + 16 * mt + (lane >> 2);
        int r1r = r0 + 8;
        #pragma unroll
        for (int nt = 0; nt < 4; nt++) {
            int col = cbase + 32 * wn + 8 * nt + 2 * (lane & 3);
            #pragma unroll
            for (int q = 0; q < 4; q++) {
                int r  = (q < 2) ? r0 : r1r;
                int cg = col + (q & 1);
                if (r < Nn) {
                    float v = acc[mt][nt][q];
                    if constexpr (MODE == M_P1P2) {
                        outf[r * NCOLS + cg] = v;
                    } else if constexpr (MODE == M_NMLP1 || MODE == M_MMLP1) {
                        outu[r * NCOLS + cg] = f2tf32(silu_f(v + bias[cg]));
                    } else if constexpr (MODE == M_NMLP2) {
                        outf[r * NCOLS + cg] = res1[r * NCOLS + cg] + g_hn[r * NCOLS + cg]
                                             + v + bias[cg];
                    } else {   // M_MMLP2
                        outf[r * NCOLS + cg] = g_h1[r * NCOLS + cg] + v + bias[cg];
                    }
                }
            }
        }
    }
}

// ---------------- edge kernel: layer1 gather -> tf32 mma.sync GEMM -> silu*cutoff -> scatter ----
#define EPB  64                 // edges per CTA (GEMM M)
#define KC   16                 // K-chunk rows
#define ASTA 260                // A smem row stride (floats)
#define ASTB 264                // B smem row stride (floats)
constexpr int A_SMEM_U32 = EPB * ASTA;
constexpr int B_SMEM_U32 = KC * ASTB;
constexpr int EDGE_DSMEM = (A_SMEM_U32 + 2 * B_SMEM_U32) * 4;

__global__ void __launch_bounds__(256, 2) edge_kernel(const float* __restrict__ x,
                                                      const int*   __restrict__ eidx,
                                                      const float* __restrict__ We1,
                                                      const float* __restrict__ be1,
                                                      const float* __restrict__ be2) {
    extern __shared__ __align__(16) uint32_t dynbuf[];
    uint32_t* As = dynbuf;
    uint32_t* Bs[2] = { dynbuf + A_SMEM_U32,
                        dynbuf + A_SMEM_U32 + B_SMEM_U32 };

    __shared__ float sDist[EPB], sCcut[EPB], sWl[Hh], sBe1[Hh], sBe2[Hh];
    __shared__ int   sRow[EPB], sCol[EPB];

    int tid  = threadIdx.x;
    int lane = tid & 31;
    int w    = tid >> 5;
    int wm   = w & 1;
    int wn   = w >> 1;
    int e0   = blockIdx.x * EPB;

    uint32_t sBu[2];
    sBu[0] = (uint32_t)__cvta_generic_to_shared(Bs[0]);
    sBu[1] = (uint32_t)__cvta_generic_to_shared(Bs[1]);

    {
        const uint32_t* src = g_We2tf;
        #pragma unroll
        for (int i = 0; i < 4; i++) {
            int idx4 = tid + i * 256;
            int k  = idx4 >> 6;
            int n4 = (idx4 & 63) << 2;
            cp_async16(sBu[0] + (k * ASTB + n4) * 4, src + k * Hh + n4);
        }
        asm volatile("cp.async.commit_group;" ::: "memory");
    }

    if (tid < EPB) {
        int e = e0 + tid;
        int r = eidx[e];
        int c = eidx[Ee + e];
        sRow[tid] = r;
        sCol[tid] = c;
        float dx = x[r * 3 + 0] - x[c * 3 + 0];
        float dy = x[r * 3 + 1] - x[c * 3 + 1];
        float dz = x[r * 3 + 2] - x[c * 3 + 2];
        float d  = sqrtf(dx * dx + dy * dy + dz * dz);
        sDist[tid] = d;
        float cc = 0.5f * (__cosf(d * (kPi / kCutoff)) + 1.0f);
        sCcut[tid] = (d <= kCutoff) ? cc : 0.0f;
        atomicAdd(&g_cnt[c], 1.0f);
    }
    sWl[tid]  = We1[(2 * Cc) * Hh + tid];
    sBe1[tid] = be1[tid];
    sBe2[tid] = be2[tid];
    __syncthreads();

    #pragma unroll 1
    for (int ei = 0; ei < 8; ei++) {
        int e = w * 8 + ei;
        float d = sDist[e];
        const float4* p1 = (const float4*)(g_P12 + sRow[e] * 512);
        const float4* p2 = (const float4*)(g_P12 + sCol[e] * 512 + 256);
        #pragma unroll
        for (int g = 0; g < 2; g++) {
            int k4 = g * 32 + lane;
            float4 a  = p1[k4];
            float4 b2 = p2[k4];
            float4 wl = ((const float4*)sWl)[k4];
            float4 bb = ((const float4*)sBe1)[k4];
            uint32_t* dst = As + e * ASTA + k4 * 4;
            dst[0] = f2tf32(silu_f(a.x + b2.x + d * wl.x + bb.x));
            dst[1] = f2tf32(silu_f(a.y + b2.y + d * wl.y + bb.y));
            dst[2] = f2tf32(silu_f(a.z + b2.z + d * wl.z + bb.z));
            dst[3] = f2tf32(silu_f(a.w + b2.w + d * wl.w + bb.w));
        }
    }
    asm volatile("cp.async.wait_group 0;" ::: "memory");
    __syncthreads();

    float acc[2][8][4];
    #pragma unroll
    for (int mt = 0; mt < 2; mt++)
        #pragma unroll
        for (int nt = 0; nt < 8; nt++)
            #pragma unroll
            for (int q = 0; q < 4; q++) acc[mt][nt][q] = 0.0f;

    int ar0 = 32 * wm + (lane >> 2);
    int bc0 = 64 * wn + (lane >> 2);
    const uint32_t* Aw = As + ar0 * ASTA + (lane & 3);

    #pragma unroll 1
    for (int kc = 0; kc < 16; kc++) {
        if (kc < 15) {
            const uint32_t* src = g_We2tf + (kc + 1) * KC * Hh;
            uint32_t dstb = sBu[(kc + 1) & 1];
            #pragma unroll
            for (int i = 0; i < 4; i++) {
                int idx4 = tid + i * 256;
                int k  = idx4 >> 6;
                int n4 = (idx4 & 63) << 2;
                cp_async16(dstb + (k * ASTB + n4) * 4, src + k * Hh + n4);
            }
            asm volatile("cp.async.commit_group;" ::: "memory");
        }
        const uint32_t* Bw = Bs[kc & 1] + (lane & 3) * ASTB + bc0;
        #pragma unroll
        for (int st = 0; st < 2; st++) {
            const uint32_t* Ab0 = Aw + kc * KC + st * 8;
            const uint32_t* Bb  = Bw + st * 8 * ASTB;
            uint32_t a[2][4];
            #pragma unroll
            for (int mt = 0; mt < 2; mt++) {
                const uint32_t* Ab = Ab0 + mt * 16 * ASTA;
                a[mt][0] = Ab[0];
                a[mt][1] = Ab[8 * ASTA];
                a[mt][2] = Ab[4];
                a[mt][3] = Ab[8 * ASTA + 4];
            }
            uint32_t b[8][2];
            #pragma unroll
            for (int nt = 0; nt < 8; nt++) {
                b[nt][0] = Bb[8 * nt];
                b[nt][1] = Bb[4 * ASTB + 8 * nt];
            }
            #pragma unroll
            for (int mt = 0; mt < 2; mt++)
                #pragma unroll
                for (int nt = 0; nt < 8; nt++)
                    mma_tf32(acc[mt][nt][0], acc[mt][nt][1],
                             acc[mt][nt][2], acc[mt][nt][3],
                             a[mt][0], a[mt][1], a[mt][2], a[mt][3],
                             b[nt][0], b[nt][1]);
        }
        if (kc < 15) asm volatile("cp.async.wait_group 0;" ::: "memory");
        __syncthreads();
    }

    #pragma unroll
    for (int mt = 0; mt < 2; mt++) {
        int r0 = 32 * wm + 16 * mt + (lane >> 2);
        int r1 = r0 + 8;
        float cc0 = sCcut[r0], cc1 = sCcut[r1];
        int base0 = sCol[r0] * Hh, base1 = sCol[r1] * Hh;
        #pragma unroll
        for (int nt = 0; nt < 8; nt++) {
            int col = 64 * wn + 8 * nt + 2 * (lane & 3);
            float b0 = sBe2[col], b1 = sBe2[col + 1];
            atomicAdd(&g_sums[base0 + col],     silu_f(acc[mt][nt][0] + b0) * cc0);
            atomicAdd(&g_sums[base0 + col + 1], silu_f(acc[mt][nt][1] + b1) * cc0);
            atomicAdd(&g_sums[base1 + col],     silu_f(acc[mt][nt][2] + b0) * cc1);
            atomicAdd(&g_sums[base1 + col + 1], silu_f(acc[mt][nt][3] + b1) * cc1);
        }
    }
}

// ---------------- launch ----------------
extern "C" void kernel_launch(void* const* d_in, const int* in_sizes, int n_in,
                              void* d_out, int out_size) {
    const float* x     = (const float*)d_in[0];
    const float* h     = (const float*)d_in[1];
    const int*   eidx  = (const int*)  d_in[2];
    const float* We1   = (const float*)d_in[3];
    const float* be1   = (const float*)d_in[4];
    const float* We2   = (const float*)d_in[5];
    const float* be2   = (const float*)d_in[6];
    const float* Wn1   = (const float*)d_in[7];
    const float* bn1   = (const float*)d_in[8];
    const float* Wn2   = (const float*)d_in[9];
    const float* bn2   = (const float*)d_in[10];
    const float* Wm1   = (const float*)d_in[11];
    const float* bm1   = (const float*)d_in[12];
    const float* Wm2   = (const float*)d_in[13];
    const float* bm2   = (const float*)d_in[14];
    const float* g1    = (const float*)d_in[15];
    const float* beta1 = (const float*)d_in[16];
    const float* g2    = (const float*)d_in[17];
    const float* beta2 = (const float*)d_in[18];

    static int attr_done = 0;
    if (!attr_done) {
        cudaFuncSetAttribute(edge_kernel,
                             cudaFuncAttributeMaxDynamicSharedMemorySize, EDGE_DSMEM);
        attr_done = 1;
    }

    const int RB = (Nn + 63) / 64;   // 157

    zero_kernel<<<(Nn * Hh + 1023) / 1024, 1024>>>();
    prepW_kernel<<<((Cc + Hh) * Hh + 255) / 256, 256>>>(We2, Wn1, Wn2, Wm1, Wm2, We1);
    ln_kernel<0><<<Nn, Cc>>>(h, g1, beta1);
    node_gemm<128, 512, M_P1P2><<<dim3(RB, 4), 256>>>(nullptr, nullptr, nullptr);
    edge_kernel<<<Ee / EPB, 256, EDGE_DSMEM>>>(x, eidx, We1, be1, be2);
    magg_kernel<<<Nn, Hh>>>();
    node_gemm<384, 256, M_NMLP1><<<dim3(RB, 2), 256>>>(bn1, nullptr, nullptr);
    node_gemm<256, 128, M_NMLP2><<<dim3(RB, 1), 256>>>(bn2, h, nullptr);
    ln_kernel<1><<<Nn, Cc>>>(h, g2, beta2);
    node_gemm<128, 256, M_MMLP1><<<dim3(RB, 2), 256>>>(bm1, nullptr, nullptr);
    node_gemm<256, 128, M_MMLP2><<<dim3(RB, 1), 256>>>(bm2, nullptr, (float*)d_out);
}